// round 12
// baseline (speedup 1.0000x reference)
#include <cuda_runtime.h>
#include <cstdint>

// LIF recurrence, forward spikes only.
// x: [T=32, B, D] fp32, out: same shape, spikes in {0.0, 1.0}.
//   mem_t = dec_{t-1} + x_t ; spike_t = mem_t > 0.5
//   dec_t = spike_t ? 0 : mem_t * 0.25        (dec_{-1} = 0)
//
// Wall time is pinned at ~45.5us = 256 MB/replay at ~74% of HBM spec; the
// only remaining lever is DRAM bytes per replay. R9/R11 L2-pinning failed,
// hypothesis: .cs STORES still ALLOCATE L2 lines -> 128 MB of write
// allocations per replay thrash the pinned input no matter its priority.
// R12: st.global.wt (write-through, no L2 allocation) for the output stream
// + L2::evict_last v8 loads pinning the whole 128 MB input. If the story is
// right, steady-state DRAM ~= writes only (~140 MB/replay).

#define THRESH 0.5f
#define DECAY  0.25f

__device__ __forceinline__ void ldg256_keep(float* d, const float* p)
{
    uint32_t r0, r1, r2, r3, r4, r5, r6, r7;
    asm volatile(
        "ld.global.L2::evict_last.v8.b32 {%0,%1,%2,%3,%4,%5,%6,%7}, [%8];"
        : "=r"(r0), "=r"(r1), "=r"(r2), "=r"(r3),
          "=r"(r4), "=r"(r5), "=r"(r6), "=r"(r7)
        : "l"(p));
    d[0] = __uint_as_float(r0); d[1] = __uint_as_float(r1);
    d[2] = __uint_as_float(r2); d[3] = __uint_as_float(r3);
    d[4] = __uint_as_float(r4); d[5] = __uint_as_float(r5);
    d[6] = __uint_as_float(r6); d[7] = __uint_as_float(r7);
}

__device__ __forceinline__ void stg128_wt(float* p, float a, float b,
                                          float c, float d)
{
    asm volatile(
        "st.global.wt.v4.f32 [%0], {%1,%2,%3,%4};"
        :: "l"(p), "f"(a), "f"(b), "f"(c), "f"(d)
        : "memory");
}

// load 2 timesteps (2 x v8) into buffer b[16]
__device__ __forceinline__ void load2(float (&b)[16], const float* __restrict__ p,
                                      long stf)
{
    ldg256_keep(&b[0], p);
    ldg256_keep(&b[8], p + stf);
}

// compute + store 2 timesteps from buffer
__device__ __forceinline__ void comp2(const float (&b)[16], float (&dec)[8],
                                      float* __restrict__ op, long stf)
{
    #pragma unroll
    for (int t = 0; t < 2; t++) {
        float s[8];
        #pragma unroll
        for (int j = 0; j < 8; j++) {
            float m = dec[j] + b[t * 8 + j];
            s[j]   = (m > THRESH) ? 1.0f : 0.0f;
            dec[j] = (m > THRESH) ? 0.0f : m * DECAY;
        }
        float* q = op + (long)t * stf;
        stg128_wt(q,     s[0], s[1], s[2], s[3]);
        stg128_wt(q + 4, s[4], s[5], s[6], s[7]);
    }
}

__global__ __launch_bounds__(128) void lif_kernel(
    const float* __restrict__ x,
    float* __restrict__ out,
    int BD)
{
    long i = (long)(blockIdx.x * blockDim.x + threadIdx.x) * 8;
    const long stf = BD;
    const float* __restrict__ xp = x + i;
    float* __restrict__       op = out + i;

    float A[16], B[16];
    float dec[8];
    #pragma unroll
    for (int j = 0; j < 8; j++) dec[j] = 0.0f;

    // 16 chunks of 2 timesteps; loads stay one chunk ahead of compute.
    load2(A, xp + 0L * 2 * stf, stf);
    load2(B, xp + 1L * 2 * stf, stf);

    #pragma unroll
    for (int c = 0; c < 16; c++) {
        if (c & 1) {
            comp2(B, dec, op + (long)c * 2 * stf, stf);
            if (c + 2 < 16) load2(B, xp + (long)(c + 2) * 2 * stf, stf);
        } else {
            comp2(A, dec, op + (long)c * 2 * stf, stf);
            if (c + 2 < 16) load2(A, xp + (long)(c + 2) * 2 * stf, stf);
        }
    }
}

extern "C" void kernel_launch(void* const* d_in, const int* in_sizes, int n_in,
                              void* d_out, int out_size)
{
    const float* x = (const float*)d_in[0];
    float* out = (float*)d_out;

    const int T = 32;
    int total = in_sizes[0];        // T * B * D
    int BD = total / T;             // 1,048,576
    int chains8 = BD / 8;           // 131,072 threads

    int threads = 128;
    int blocks = chains8 / threads; // exact: 1024
    lif_kernel<<<blocks, threads>>>(x, out, BD);
}

// round 13
// speedup vs baseline: 1.0766x; 1.0766x over previous
#include <cuda_runtime.h>
#include <cstdint>

// LIF recurrence, forward spikes only.
// x: [T=32, B, D] fp32, out: same shape, spikes {0.0, 1.0}.
//   mem_t = dec_{t-1} + x_t ; spike_t = mem_t > 0.5
//   dec_t = spike_t ? 0 : mem_t * 0.25       (dec_{-1} = 0)
//
// R2-R12: wall pinned at ~45.4us = 256 MB/replay @74% of HBM spec across all
// fine-grained LDG/STG schemes; L2-residency levers all falsified. Remaining
// structural lever: R/W bus turnaround from 512B-granular interleaved
// reads+writes. R13: phase separation. Each block TMA-bulk-reads its whole
// 64 KB working set (32 timesteps x 2 KB slab) into smem, computes the LIF
// recurrence in-place, then TMA-bulk-writes 64 KB back. Per-stream burst
// granularity 512B -> 64KB. 2 CTAs/SM so phases of one CTA overlap compute
// of the other.

#define THRESH 0.5f
#define DECAY  0.25f
#define T_STEPS 32
#define SLAB    512                       // floats per timestep per block (2 KB)
#define SLAB_BYTES (SLAB * 4)
#define TPB     128                       // 1 float4 per thread per timestep
#define SMEM_DATA_BYTES (T_STEPS * SLAB_BYTES)   // 64 KB
#define SMEM_TOTAL (SMEM_DATA_BYTES + 16)

__device__ __forceinline__ uint32_t smem_u32(const void* p)
{
    uint32_t a;
    asm("{ .reg .u64 t; cvta.to.shared.u64 t, %1; cvt.u32.u64 %0, t; }"
        : "=r"(a) : "l"(p));
    return a;
}

__global__ __launch_bounds__(TPB) void lif_phase_kernel(
    const float* __restrict__ x,
    float* __restrict__ out,
    int BD)
{
    extern __shared__ __align__(128) float s[];           // [T_STEPS][SLAB]
    uint64_t* mbar = reinterpret_cast<uint64_t*>(s + T_STEPS * SLAB);

    const int  tid  = threadIdx.x;
    const long col0 = (long)blockIdx.x * SLAB;

    if (tid == 0) {
        uint32_t b = smem_u32(mbar);
        asm volatile("mbarrier.init.shared.b64 [%0], 1;" :: "r"(b) : "memory");
        asm volatile("fence.proxy.async.shared::cta;" ::: "memory");
    }
    __syncthreads();

    // ---- Phase 1: bulk READ burst (32 x 2 KB, one mbarrier) ----
    if (tid == 0) {
        uint32_t b = smem_u32(mbar);
        asm volatile("mbarrier.arrive.expect_tx.shared.b64 _, [%0], %1;"
                     :: "r"(b), "r"(SMEM_DATA_BYTES) : "memory");
        #pragma unroll
        for (int t = 0; t < T_STEPS; t++) {
            uint32_t dst = smem_u32(&s[t * SLAB]);
            const float* src = x + (long)t * BD + col0;
            asm volatile(
                "cp.async.bulk.shared::cta.global.mbarrier::complete_tx::bytes "
                "[%0], [%1], %2, [%3];"
                :: "r"(dst), "l"(src), "r"(SLAB_BYTES), "r"(b) : "memory");
        }
    }
    // all threads wait for the full 64 KB
    {
        uint32_t b = smem_u32(mbar);
        uint32_t done;
        asm volatile(
            "{\n\t.reg .pred p;\n\t"
            "mbarrier.try_wait.parity.acquire.cta.shared::cta.b64 p, [%1], 0;\n\t"
            "selp.b32 %0, 1, 0, p;\n\t}"
            : "=r"(done) : "r"(b) : "memory");
        if (!done) {
            asm volatile(
                "{\n\t.reg .pred P1;\n\t"
                "W_%=:\n\t"
                "mbarrier.try_wait.parity.acquire.cta.shared::cta.b64 P1, [%0], 0, 0x989680;\n\t"
                "@P1 bra.uni D_%=;\n\t"
                "bra.uni W_%=;\n\t"
                "D_%=:\n\t}"
                :: "r"(b) : "memory");
        }
    }

    // ---- Phase 2: compute in-place in smem ----
    {
        float4* sv = reinterpret_cast<float4*>(s);
        const int j = tid;                 // float4 index within slab (128 per row)
        float4 dec = make_float4(0.0f, 0.0f, 0.0f, 0.0f);
        #pragma unroll
        for (int t = 0; t < T_STEPS; t++) {
            float4 v = sv[t * (SLAB / 4) + j];
            float4 sp;
            float mx = dec.x + v.x, my = dec.y + v.y,
                  mz = dec.z + v.z, mw = dec.w + v.w;
            sp.x = (mx > THRESH) ? 1.0f : 0.0f;
            sp.y = (my > THRESH) ? 1.0f : 0.0f;
            sp.z = (mz > THRESH) ? 1.0f : 0.0f;
            sp.w = (mw > THRESH) ? 1.0f : 0.0f;
            dec.x = (mx > THRESH) ? 0.0f : mx * DECAY;
            dec.y = (my > THRESH) ? 0.0f : my * DECAY;
            dec.z = (mz > THRESH) ? 0.0f : mz * DECAY;
            dec.w = (mw > THRESH) ? 0.0f : mw * DECAY;
            sv[t * (SLAB / 4) + j] = sp;
        }
    }
    __syncthreads();
    // make generic-proxy smem writes visible to the async (TMA) proxy
    asm volatile("fence.proxy.async.shared::cta;" ::: "memory");
    __syncthreads();

    // ---- Phase 3: bulk WRITE burst (32 x 2 KB) ----
    if (tid == 0) {
        #pragma unroll
        for (int t = 0; t < T_STEPS; t++) {
            uint32_t src = smem_u32(&s[t * SLAB]);
            float* dst = out + (long)t * BD + col0;
            asm volatile(
                "cp.async.bulk.global.shared::cta.bulk_group [%0], [%1], %2;"
                :: "l"(dst), "r"(src), "r"(SLAB_BYTES) : "memory");
        }
        asm volatile("cp.async.bulk.commit_group;" ::: "memory");
        asm volatile("cp.async.bulk.wait_group 0;" ::: "memory");
    }
}

extern "C" void kernel_launch(void* const* d_in, const int* in_sizes, int n_in,
                              void* d_out, int out_size)
{
    const float* x = (const float*)d_in[0];
    float* out = (float*)d_out;

    const int T = 32;
    int total = in_sizes[0];        // T * B * D
    int BD = total / T;             // 1,048,576
    int blocks = BD / SLAB;         // 2048

    static bool attr_set = false;
    if (!attr_set) {
        cudaFuncSetAttribute(lif_phase_kernel,
                             cudaFuncAttributeMaxDynamicSharedMemorySize,
                             SMEM_TOTAL);
        attr_set = true;
    }

    lif_phase_kernel<<<blocks, TPB, SMEM_TOTAL>>>(x, out, BD);
}

// round 14
// speedup vs baseline: 1.1338x; 1.0531x over previous
#include <cuda_runtime.h>

// LIF recurrence, forward spikes only.
// x: [T=32, B, D] fp32, out: same shape, spikes in {0.0, 1.0}.
//   mem_t = dec_{t-1} + x_t ; spike_t = mem_t > 0.5
//   dec_t = spike_t ? 0 : mem_t * 0.25        (dec_{-1} = 0)
//
// R14 = R4 (best: 36.7us ncu, DRAM 74.1%) with warp-level burst batching:
// compute overwrites the load buffer in place with spikes, then 8 STG.128
// issue back-to-back -> each warp alternates a 4 KB contiguous read burst
// and a 4 KB contiguous write burst instead of dribbling interleaved
// 512 B stores. Zero extra registers; occupancy unchanged.

#define THRESH 0.5f
#define DECAY  0.25f

__device__ __forceinline__ void load8(float4 (&b)[8], const float4* __restrict__ p,
                                      long st)
{
    #pragma unroll
    for (int k = 0; k < 8; k++)
        b[k] = __ldcs(p + (long)k * st);
}

// Compute 8 timesteps; spikes overwrite the load buffer in place.
__device__ __forceinline__ void compute8(float4 (&b)[8], float4& dec)
{
    #pragma unroll
    for (int k = 0; k < 8; k++) {
        float mx = dec.x + b[k].x;
        float my = dec.y + b[k].y;
        float mz = dec.z + b[k].z;
        float mw = dec.w + b[k].w;

        b[k].x = (mx > THRESH) ? 1.0f : 0.0f;
        b[k].y = (my > THRESH) ? 1.0f : 0.0f;
        b[k].z = (mz > THRESH) ? 1.0f : 0.0f;
        b[k].w = (mw > THRESH) ? 1.0f : 0.0f;

        dec.x = (mx > THRESH) ? 0.0f : mx * DECAY;
        dec.y = (my > THRESH) ? 0.0f : my * DECAY;
        dec.z = (mz > THRESH) ? 0.0f : mz * DECAY;
        dec.w = (mw > THRESH) ? 0.0f : mw * DECAY;
    }
}

// 8 back-to-back streaming stores: one 4 KB same-direction warp burst.
__device__ __forceinline__ void store8(const float4 (&b)[8],
                                       float4* __restrict__ op, long st)
{
    #pragma unroll
    for (int k = 0; k < 8; k++)
        __stcs(op + (long)k * st, b[k]);
}

__global__ __launch_bounds__(256) void lif_kernel(
    const float4* __restrict__ x,
    float4* __restrict__ out,
    int chains4)   // BD / 4
{
    int i = blockIdx.x * blockDim.x + threadIdx.x;
    const long st = chains4;
    const float4* __restrict__ xp = x + i;
    float4* __restrict__       op = out + i;

    float4 A[8], B[8];
    float4 dec = make_float4(0.0f, 0.0f, 0.0f, 0.0f);

    load8(A, xp, st);                    // t 0..7   in flight
    load8(B, xp + 8 * st, st);           // t 8..15  in flight

    compute8(A, dec);
    store8(A, op, st);
    load8(A, xp + 16 * st, st);          // t 16..23 in flight

    compute8(B, dec);
    store8(B, op + 8 * st, st);
    load8(B, xp + 24 * st, st);          // t 24..31 in flight

    compute8(A, dec);
    store8(A, op + 16 * st, st);

    compute8(B, dec);
    store8(B, op + 24 * st, st);
}

extern "C" void kernel_launch(void* const* d_in, const int* in_sizes, int n_in,
                              void* d_out, int out_size)
{
    const float* x = (const float*)d_in[0];
    float* out = (float*)d_out;

    const int T = 32;
    int total = in_sizes[0];        // T * B * D
    int BD = total / T;             // 1,048,576
    int chains4 = BD / 4;           // 262,144

    int threads = 256;
    int blocks = chains4 / threads; // exact: 1024
    lif_kernel<<<blocks, threads>>>((const float4*)x, (float4*)out, chains4);
}